// round 17
// baseline (speedup 1.0000x reference)
#include <cuda_runtime.h>
#include <cuda_bf16.h>

// Problem constants
#define BB 8
#define LL 8192
#define DD 512
#define SF 4
#define RR 32                 // rows per chunk
#define CH (LL / RR)          // 256 chunks per batch
#define NCHUNK (BB * CH)      // 2048 total chunks
#define OUT_L (LL / SF)       // 2048
#define D4 (DD / 4)           // 128 float4 lanes
#define OUTG (RR / SF)        // 8 output rows per chunk
#define NSUP 16               // supers per batch
#define SUPC (CH / NSUP)      // 16 chunks per super
#define GRIDN 1024            // 8 batch-groups x 128 blocks, all co-resident
#define BPB (GRIDN / BB)      // 128 blocks per batch
#define CPB 2                 // chunks per block

// Scratch (L2-resident)
__device__ float g_part[BB][CH][DD];        // per-chunk aggregates (4 MB)
__device__ float g_sup[BB][NSUP][DD];       // per-super sums (256 KB)
__device__ unsigned g_barA[BB];             // per-batch barrier 1
__device__ unsigned g_barB[BB];             // per-batch barrier 2
__device__ unsigned g_done;                 // cleanup counter

__device__ __forceinline__ unsigned ld_acq_u(const unsigned* p) {
    unsigned v;
    asm volatile("ld.acquire.gpu.u32 %0, [%1];" : "=r"(v) : "l"(p) : "memory");
    return v;
}

// Per-batch barrier over BPB blocks: safe because ALL GRIDN blocks are
// co-resident (launch_bounds(128,8): 1024 <= 148*8), so any subset barrier
// cannot deadlock.
__device__ __forceinline__ void bsync(unsigned* ctr) {
    __syncthreads();
    if (threadIdx.x == 0) {
        __threadfence();                       // release prior writes
        atomicAdd(ctr, 1u);
        while (ld_acq_u(ctr) < BPB) __nanosleep(128);
    }
    __syncthreads();
    __threadfence();                           // acquire others' writes
}

__global__ __launch_bounds__(128, 8) void k_all(const float* __restrict__ x,
                                                float* __restrict__ out) {
    const int tid = threadIdx.x;
    const int d4 = tid;
    const int b = blockIdx.x / BPB;            // batch group
    const int r = blockIdx.x % BPB;            // rank within batch (0..127)

    // ── Phase A: two chunk scans within this batch; partials -> out ──
#pragma unroll
    for (int u = 0; u < CPB; ++u) {
        const int c = r * CPB + u;             // chunk within batch
        const float4* xp = reinterpret_cast<const float4*>(
            x + ((size_t)b * LL + (size_t)c * RR) * DD) + d4;
        float4* op = reinterpret_cast<float4*>(
            out + ((size_t)b * OUT_L + (size_t)c * OUTG) * DD) + d4;

        float4 acc = make_float4(0.f, 0.f, 0.f, 0.f);
#pragma unroll
        for (int g = 0; g < OUTG; ++g) {
            float4 v0 = __ldcs(xp + (size_t)(g * SF + 0) * D4);
            float4 v1 = __ldcs(xp + (size_t)(g * SF + 1) * D4);
            float4 v2 = __ldcs(xp + (size_t)(g * SF + 2) * D4);
            float4 v3 = __ldcs(xp + (size_t)(g * SF + 3) * D4);
            acc.x += (v0.x + v1.x) + (v2.x + v3.x);
            acc.y += (v0.y + v1.y) + (v2.y + v3.y);
            acc.z += (v0.z + v1.z) + (v2.z + v3.z);
            acc.w += (v0.w + v1.w) + (v2.w + v3.w);
            op[(size_t)g * D4] = acc;          // unscaled partial prefix
        }
        reinterpret_cast<float4*>(g_part[b][c])[d4] = acc;
    }

    bsync(&g_barA[b]);

    // ── Phase B: super sums for this batch (ranks 0..15) ──
    if (r < NSUP) {
        const int s = r;
        float4 sum = make_float4(0.f, 0.f, 0.f, 0.f);
#pragma unroll
        for (int k = 0; k < SUPC; ++k) {
            float4 v = reinterpret_cast<const float4*>(g_part[b][s * SUPC + k])[d4];
            sum.x += v.x; sum.y += v.y; sum.z += v.z; sum.w += v.w;
        }
        reinterpret_cast<float4*>(g_sup[b][s])[d4] = sum;
    }

    bsync(&g_barB[b]);

    // ── Phase C: base from hierarchy (L2-hot), in-place RMW of out ──
#pragma unroll
    for (int u = 0; u < CPB; ++u) {
        const int c = r * CPB + u;
        const int s = c >> 4;
        const int nin = c & (SUPC - 1);

        float4 base = make_float4(0.f, 0.f, 0.f, 0.f);
        for (int j = 0; j < s; ++j) {
            float4 v = reinterpret_cast<const float4*>(g_sup[b][j])[d4];
            base.x += v.x; base.y += v.y; base.z += v.z; base.w += v.w;
        }
        for (int j = 0; j < nin; ++j) {
            float4 v = reinterpret_cast<const float4*>(g_part[b][s * SUPC + j])[d4];
            base.x += v.x; base.y += v.y; base.z += v.z; base.w += v.w;
        }

        float4* op = reinterpret_cast<float4*>(
            out + ((size_t)b * OUT_L + (size_t)c * OUTG) * DD) + d4;
#pragma unroll
        for (int g = 0; g < OUTG; ++g) {
            const float inv = 1.0f / (float)(c * RR + g * SF + SF);
            float4 v = op[(size_t)g * D4];     // L2 hit: written this kernel
            v.x = (v.x + base.x) * inv;
            v.y = (v.y + base.y) * inv;
            v.z = (v.z + base.z) * inv;
            v.w = (v.w + base.w) * inv;
            op[(size_t)g * D4] = v;
        }
    }

    // ── Cleanup: last block of the whole grid resets counters for replay ──
    __syncthreads();
    if (tid == 0) {
        __threadfence();
        unsigned v = atomicAdd(&g_done, 1u);
        if (v == GRIDN - 1) {
#pragma unroll
            for (int j = 0; j < BB; ++j) { g_barA[j] = 0u; g_barB[j] = 0u; }
            g_done = 0u;
            __threadfence();
        }
    }
}

extern "C" void kernel_launch(void* const* d_in, const int* in_sizes, int n_in,
                              void* d_out, int out_size) {
    const float* x = (const float*)d_in[0];
    float* out = (float*)d_out;

    k_all<<<GRIDN, 128>>>(x, out);
}